// round 16
// baseline (speedup 1.0000x reference)
#include <cuda_runtime.h>
#include <cuda_bf16.h>
#include <cstdint>
#include <cstddef>

#define NS   8192
#define KTOT 11520

__constant__ int cPERM[45] = {
    0,1,2,3,4,5,6, 7,8,9,
    10,11,12,13,14,15,16,17,18,19,20,21,22,23,
    26,27, 28,29, 24,25,
    30,31,32,33,34,35,36,37,38,39,40,41,42,43,44
};
__constant__ int cFOFF[45] = {
    0,300,1300,2300,2800,2950,2962,
    2993,2993,2993,
    3023,3023,3023,3023,3023,3023,3023,3023,3023,3023,3023,3023,3023,3023,
    3223,3223, 53223,53223, 103223,103223,
    123223,123223,123223,123223,123223,123223,123223,123223,
    123223,123223,123223,123223,123223,123223,123223
};
__constant__ int cVOC[24] = {
    300,1000,1000,500,150,12,31,30,30,30,
    200,200,200,200,200,200,200,200,200,200,200,200,200,200
};
__constant__ int cPBASE[24] = {
    0,300,1300,2300,2800,2950,2962,2993,3023,3053,
    3083,3283,3483,3683,3883,4083,4283,4483,4683,4883,5083,5283,5483,5683
};
#define PROWS 5883

// device-global scratch (no cudaMalloc allowed)
__device__ __align__(16) float g_x1p[2*NS*32];
__device__ __align__(16) float g_x1s[NS*32];
__device__ __align__(16) float g_fmp[2*NS];
__device__ __align__(16) float g_fms[NS];
__device__ __align__(16) float g_acc[128];       // [sum1 x32 | .. | w~ x32 | C]
__device__ __align__(16) float g_M[1024];        // x1 second moments (atomic)
__device__ __align__(16) float g_ssmall[4*NS*64];
__device__ __align__(16) float g_P[PROWS*32];
__device__ __align__(16) unsigned char g_Bh[180*4096];
__device__ __align__(16) unsigned char g_Bl[180*4096];

// ---------------- helpers ----------------
__device__ __forceinline__ uint32_t smem_u32(const void* p) {
    uint32_t r;
    asm("{ .reg .u64 t; cvta.to.shared.u64 t, %1; cvt.u32.u64 %0, t; }"
        : "=r"(r) : "l"(p));
    return r;
}
__device__ __forceinline__ uint32_t cvt2(float hi, float lo) {
    uint32_t r;
    asm("cvt.rn.bf16x2.f32 %0, %1, %2;" : "=r"(r) : "f"(hi), "f"(lo));
    return r;
}
__device__ __forceinline__ void ldsm4(uint32_t* r, uint32_t addr) {
    asm volatile("ldmatrix.sync.aligned.m8n8.x4.shared.b16 {%0,%1,%2,%3}, [%4];"
        : "=r"(r[0]), "=r"(r[1]), "=r"(r[2]), "=r"(r[3]) : "r"(addr));
}
__device__ __forceinline__ void mma16816(float* d, const uint32_t* a, const uint32_t* b) {
    asm volatile(
        "mma.sync.aligned.m16n8k16.row.col.f32.bf16.bf16.f32 "
        "{%0,%1,%2,%3}, {%4,%5,%6,%7}, {%8,%9}, {%0,%1,%2,%3};"
        : "+f"(d[0]), "+f"(d[1]), "+f"(d[2]), "+f"(d[3])
        : "r"(a[0]), "r"(a[1]), "r"(a[2]), "r"(a[3]), "r"(b[0]), "r"(b[1]));
}
__device__ __forceinline__ void cpa16(uint32_t dst, const void* src) {
    asm volatile("cp.async.cg.shared.global [%0], [%1], 16;" :: "r"(dst), "l"(src));
}
__device__ __forceinline__ void cpa_commit() {
    asm volatile("cp.async.commit_group;" ::: "memory");
}
template<int N>
__device__ __forceinline__ void cpa_wait() {
    asm volatile("cp.async.wait_group %0;" :: "n"(N) : "memory");
}

// ---------------- k1 smem layout ----------------
#define A_IMG   9216u
#define SM_A(buf,img)  ((uint32_t)(((buf)*2u + (img)) * A_IMG))
#define B_IMG   4608u
#define SM_B(buf,img)  ((uint32_t)(36864u + ((buf)*2u + (img)) * B_IMG))
#define SM_IDX  73728u
#define SM_XVo  79104u
#define K1_DYN  84480u

// ---------------------------------------------------------------------------
// fusedAll: grid 1792 x 256.
// ---------------------------------------------------------------------------
__global__ __launch_bounds__(256) void fusedall_kernel(const int*   __restrict__ Xi,
                                                       const float* __restrict__ Xv,
                                                       const float* __restrict__ W1,
                                                       const float* __restrict__ W2,
                                                       const float* __restrict__ l1w)
{
    const int t = threadIdx.x;

    if (blockIdx.x >= 768) {
        const int lane = t & 31;
        const int n = (blockIdx.x - 768) * 8 + (t >> 5);

        float s[8];
#pragma unroll
        for (int i = 0; i < 8; ++i) s[i] = 0.f;
        float q = 0.f, fm = 0.f;

#pragma unroll
        for (int f = 0; f < 24; ++f) {
            const int   xi = Xi[(size_t)n * 45 + cPERM[f]];
            const float xv = Xv[(size_t)n * 45 + cPERM[f]];
            const int   row = xi + cFOFF[f];
            const float4* r4 = (const float4*)(W2 + (size_t)row * 256) + lane * 2;
            float4 a = r4[0], b = r4[1];
            float e0 = a.x*xv, e1 = a.y*xv, e2 = a.z*xv, e3 = a.w*xv;
            float e4 = b.x*xv, e5 = b.y*xv, e6 = b.z*xv, e7 = b.w*xv;
            s[0]+=e0; s[1]+=e1; s[2]+=e2; s[3]+=e3;
            s[4]+=e4; s[5]+=e5; s[6]+=e6; s[7]+=e7;
            q = fmaf(e0,e0,q); q = fmaf(e1,e1,q); q = fmaf(e2,e2,q); q = fmaf(e3,e3,q);
            q = fmaf(e4,e4,q); q = fmaf(e5,e5,q); q = fmaf(e6,e6,q); q = fmaf(e7,e7,q);
            if (lane == f) fm = fmaf(W1[row], xv, fm);
        }

        float* dst = g_ssmall + ((size_t)(lane >> 3) * NS + n) * 64 + (lane & 7) * 8;
        *(float4*)(dst)     = make_float4(s[0], s[1], s[2], s[3]);
        *(float4*)(dst + 4) = make_float4(s[4], s[5], s[6], s[7]);

        float val = fm - 0.5f * q;
#pragma unroll
        for (int o = 16; o > 0; o >>= 1) val += __shfl_xor_sync(0xffffffffu, val, o);
        if (lane == 0) g_fms[n] = val;
        return;
    }

    if (blockIdx.x == 0 && t < 128) g_acc[t] = 0.f;
    if (blockIdx.x == 1) {
#pragma unroll
        for (int i = 0; i < 4; ++i) g_M[t + i * 256] = 0.f;
    }

    if (blockIdx.x < 180 && t < 128) {
        const int sid = blockIdx.x;
        const int q = sid / 45, f = sid % 45;
        const int j  = t >> 2;
        const int c0 = (t & 3) * 16;
        const float* src = l1w + (size_t)j * KTOT + f * 256 + q * 64 + c0;
        unsigned char* bh = g_Bh + (size_t)sid * 4096;
        unsigned char* bl = g_Bl + (size_t)sid * 4096;
#pragma unroll
        for (int i = 0; i < 16; i += 2) {
            float a = src[i], b = src[i+1];
            uint32_t h2 = cvt2(b, a);
            float fa = __uint_as_float(h2 << 16);
            float fb = __uint_as_float(h2 & 0xffff0000u);
            uint32_t l2 = cvt2(b - fb, a - fa);
            uint32_t off = (uint32_t)(j * 128 + (c0 + i) * 2);
            *(uint32_t*)(bh + off) = h2;
            *(uint32_t*)(bl + off) = l2;
        }
    }

    const int f = blockIdx.x >> 5;
    const int v0 = (blockIdx.x & 31) * 32;
    if (v0 >= cVOC[f]) return;
    __shared__ __align__(16) float sl[32 * 260];
    for (int i = t; i < 8192; i += 256)
        sl[(i >> 8) * 260 + (i & 255)] = l1w[(size_t)(i >> 8) * KTOT + f * 256 + (i & 255)];
    __syncthreads();

    const int rloc = t >> 3;
    const int j0   = (t & 7) * 4;
    const int v = v0 + rloc;
    if (v >= cVOC[f]) return;
    const float* wrow = W2 + (size_t)(v + cFOFF[f]) * 256;
    float acc0 = 0.f, acc1 = 0.f, acc2 = 0.f, acc3 = 0.f;
    for (int d = 0; d < 256; d += 4) {
        float4 w = *(const float4*)(wrow + d);
        float4 a0 = *(const float4*)(sl + (j0+0) * 260 + d);
        float4 a1 = *(const float4*)(sl + (j0+1) * 260 + d);
        float4 a2 = *(const float4*)(sl + (j0+2) * 260 + d);
        float4 a3 = *(const float4*)(sl + (j0+3) * 260 + d);
        acc0 += w.x*a0.x + w.y*a0.y + w.z*a0.z + w.w*a0.w;
        acc1 += w.x*a1.x + w.y*a1.y + w.z*a1.z + w.w*a1.w;
        acc2 += w.x*a2.x + w.y*a2.y + w.z*a2.z + w.w*a2.w;
        acc3 += w.x*a3.x + w.y*a3.y + w.z*a3.z + w.w*a3.w;
    }
    float* dst = g_P + (size_t)(cPBASE[f] + v) * 32 + j0;
    dst[0] = acc0; dst[1] = acc1; dst[2] = acc2; dst[3] = acc3;
}

// ---- k1 inner-phase helpers ----
__device__ __forceinline__ void convert_store(const float4* v, float xv,
    unsigned char* Ah, unsigned char* Al, uint32_t aw,
    float* s, float& qsum)
{
#pragma unroll
    for (int i = 0; i < 4; ++i) {
        float4 vv = v[i];
        float e0 = vv.x * xv, e1 = vv.y * xv;
        float e2 = vv.z * xv, e3 = vv.w * xv;
        uint32_t h01 = cvt2(e1, e0), h23 = cvt2(e3, e2);
        float f0 = __uint_as_float(h01 << 16);
        float f1 = __uint_as_float(h01 & 0xffff0000u);
        float f2 = __uint_as_float(h23 << 16);
        float f3 = __uint_as_float(h23 & 0xffff0000u);
        uint32_t l01 = cvt2(e1 - f1, e0 - f0), l23 = cvt2(e3 - f3, e2 - f2);
        *(uint2*)(Ah + aw + i * 8) = make_uint2(h01, h23);
        *(uint2*)(Al + aw + i * 8) = make_uint2(l01, l23);
        const int ii = i * 4;
        s[ii+0] += e0; qsum = fmaf(e0, e0, qsum);
        s[ii+1] += e1; qsum = fmaf(e1, e1, qsum);
        s[ii+2] += e2; qsum = fmaf(e2, e2, qsum);
        s[ii+3] += e3; qsum = fmaf(e3, e3, qsum);
    }
}

__device__ __forceinline__ void mma_stage(uint32_t aAh, uint32_t aAl,
    uint32_t aBh, uint32_t aBl, float (&acc)[2][4])
{
#pragma unroll
    for (int k = 0; k < 4; ++k) {
        uint32_t Afh[4], Afl[4], Bh[4], Bl[4];
        ldsm4(Afh, aAh + k * 32);
        ldsm4(Afl, aAl + k * 32);
        ldsm4(Bh,  aBh + k * 32);
        ldsm4(Bl,  aBl + k * 32);
        mma16816(acc[0], Afh, &Bh[0]);
        mma16816(acc[1], Afh, &Bh[2]);
        mma16816(acc[0], Afh, &Bl[0]);
        mma16816(acc[1], Afh, &Bl[2]);
        mma16816(acc[0], Afl, &Bh[0]);
        mma16816(acc[1], Afl, &Bh[2]);
    }
}

// ---------------------------------------------------------------------------
// k1: BIG fields only. 256 blocks x 256 threads, 2 CTAs/SM. (R11 version)
// ---------------------------------------------------------------------------
__global__ void __launch_bounds__(256, 2) k1_kernel(
    const int*   __restrict__ Xi,
    const float* __restrict__ Xv,
    const float* __restrict__ W1,
    const float* __restrict__ W2)
{
    extern __shared__ unsigned char dyn[];
    const uint32_t sbase = smem_u32(dyn);

    const int t    = threadIdx.x;
    const int wid  = t >> 5, lane = t & 31;
    const int tile = blockIdx.x >> 1, ks = blockIdx.x & 1;
    const int n0   = tile * 64;

    int*   sIdx = (int*)(dyn + SM_IDX);
    float* sXv  = (float*)(dyn + SM_XVo);
    for (int i = t; i < 64 * 21; i += 256) {
        const int smp = i / 21, fi = i - smp * 21;
        sIdx[i] = Xi[(size_t)(n0 + smp) * 45 + cPERM[24 + fi]] + cFOFF[24 + fi];
        sXv[i]  = Xv[(size_t)(n0 + smp) * 45 + cPERM[24 + fi]];
    }
    __syncthreads();

    const int smp = t >> 2, p = t & 3;
    const uint32_t aw = (uint32_t)(smp * 144 + p * 32);

    const int wm = wid & 3, nh = wid >> 2;
    const uint32_t a_row = (uint32_t)(wm * 16 + ((lane >> 3) & 1) * 8 + (lane & 7));
    const uint32_t a_col = (uint32_t)((lane >> 4) * 16);
    const uint32_t b_row = (uint32_t)(nh * 16 + (lane & 7) + ((lane >> 4) << 3));
    const uint32_t b_col = (uint32_t)(((lane >> 3) & 1) * 16);
    const uint32_t aoff  = a_row * 144 + a_col;
    const uint32_t boff  = b_row * 144 + b_col;

    const int bc = t & 255;
    const uint32_t bso = (uint32_t)((bc >> 3) * 128 + (bc & 7) * 16);
    const uint32_t bdo = (uint32_t)((bc >> 3) * 144 + (bc & 7) * 16);

    float acc[2][4];
#pragma unroll
    for (int i = 0; i < 2; ++i)
#pragma unroll
        for (int j = 0; j < 4; ++j) acc[i][j] = 0.f;

    float s[16];
#pragma unroll
    for (int i = 0; i < 16; ++i) s[i] = 0.f;
    float sq2 = 0.f, qsum = 0.f, fm1 = 0.f;

    float4 v[2][4];
    float  xvq[2], w1q[2];

#define ISSUE_B(tgt, BUF)  do {                                              \
        const int fi_ = (tgt) < 21 ? (tgt) : (tgt) - 21;                     \
        const size_t sb_ = (size_t)((ks * 2 + ((tgt) >= 21)) * 45 + 24 + fi_) * 4096; \
        cpa16(sbase + SM_B((BUF), 0) + bdo, g_Bh + sb_ + bso);               \
        cpa16(sbase + SM_B((BUF), 1) + bdo, g_Bl + sb_ + bso);               \
        cpa_commit();                                                        \
    } while (0)

#define LOAD_A(tgt, AB)  do {                                                \
        const int fi_ = (tgt) < 21 ? (tgt) : (tgt) - 21;                     \
        const int qg_ = ks * 2 + ((tgt) >= 21);                              \
        const int idx_ = sIdx[smp * 21 + fi_];                               \
        xvq[AB] = sXv[smp * 21 + fi_];                                       \
        w1q[AB] = (ks == 0 && (tgt) < 21 && p == 0) ? W1[idx_] : 0.f;        \
        const float4* src_ = (const float4*)(W2 + (size_t)idx_ * 256)        \
                             + qg_ * 16 + p * 4;                             \
        v[AB][0] = src_[0]; v[AB][1] = src_[1];                              \
        v[AB][2] = src_[2]; v[AB][3] = src_[3];                              \
    } while (0)

#define FOLD(qg)  do {                                                       \
        const float4* ssm_ = (const float4*)(g_ssmall                        \
            + ((size_t)(qg) * NS + n0 + smp) * 64 + p * 16);                 \
        float4 a0_ = ssm_[0], a1_ = ssm_[1], a2_ = ssm_[2], a3_ = ssm_[3];   \
        s[0]+=a0_.x; s[1]+=a0_.y; s[2]+=a0_.z; s[3]+=a0_.w;                  \
        s[4]+=a1_.x; s[5]+=a1_.y; s[6]+=a1_.z; s[7]+=a1_.w;                  \
        s[8]+=a2_.x; s[9]+=a2_.y; s[10]+=a2_.z; s[11]+=a2_.w;                \
        s[12]+=a3_.x; s[13]+=a3_.y; s[14]+=a3_.z; s[15]+=a3_.w;              \
        float loc_ = 0.f;                                                    \
        for (int i2 = 0; i2 < 16; ++i2) { loc_ += s[i2]*s[i2]; s[i2] = 0.f; }\
        sq2 += loc_;                                                         \
    } while (0)

#define STAGE(st, AB, BB, PRE, WAITN)  do {                                  \
        if (PRE) ISSUE_B((st) + 2, ((BB) + 2) & 3);                          \
        if ((st) == 21) FOLD(ks * 2);                                        \
        fm1 += w1q[AB] * xvq[AB];                                            \
        convert_store(v[AB], xvq[AB], dyn + SM_A(AB,0), dyn + SM_A(AB,1),    \
                      aw, s, qsum);                                          \
        if (PRE) LOAD_A((st) + 2, AB);                                       \
        cpa_wait<WAITN>();                                                   \
        __syncthreads();                                                     \
        mma_stage(sbase + SM_A(AB,0) + aoff, sbase + SM_A(AB,1) + aoff,      \
                  sbase + SM_B(BB,0) + boff, sbase + SM_B(BB,1) + boff, acc);\
    } while (0)

    ISSUE_B(0, 0);
    ISSUE_B(1, 1);
    LOAD_A(0, 0);
    LOAD_A(1, 1);

    for (int ii = 0; ii < 40; ii += 4) {
        STAGE(ii + 0, 0, 0, true, 2);
        STAGE(ii + 1, 1, 1, true, 2);
        STAGE(ii + 2, 0, 2, true, 2);
        STAGE(ii + 3, 1, 3, true, 2);
    }
    STAGE(40, 0, 0, false, 1);
    STAGE(41, 1, 1, false, 0);

    FOLD(ks * 2 + 1);

#undef STAGE
#undef FOLD
#undef LOAD_A
#undef ISSUE_B

    float val = fm1 + 0.5f * sq2 - 0.5f * qsum;
    val += __shfl_xor_sync(0xffffffffu, val, 1);
    val += __shfl_xor_sync(0xffffffffu, val, 2);
    if ((t & 3) == 0) g_fmp[ks * NS + n0 + smp] = val;

    {
        const int r0 = n0 + wm * 16 + (lane >> 2);
        const int cb = nh * 16 + (lane & 3) * 2;
        float* dst = g_x1p + (size_t)ks * NS * 32;
#pragma unroll
        for (int nt = 0; nt < 2; ++nt) {
            const int c = cb + nt * 8;
            *(float2*)(dst + (size_t)r0       * 32 + c) = make_float2(acc[nt][0], acc[nt][1]);
            *(float2*)(dst + (size_t)(r0 + 8) * 32 + c) = make_float2(acc[nt][2], acc[nt][3]);
        }
    }
}

// ---------------------------------------------------------------------------
// statsM: combine x1 -> g_x1s, column sums -> g_acc[0..31], second moments
// reduced in smem then atomicAdd into g_M. grid 128 x 256.
// ---------------------------------------------------------------------------
__global__ __launch_bounds__(256) void statsM_kernel(const int*   __restrict__ Xi,
                                                     const float* __restrict__ Xv)
{
    __shared__ int   sXi[64*24];
    __shared__ float sXvs[64*24];
    __shared__ float sMw[8*1024];
    __shared__ float sS[32];
    const int t = threadIdx.x;
    const int rbase = blockIdx.x * 64;

    for (int i = t; i < 64 * 24; i += 256) {
        const int row = i / 24, f = i - row * 24;
        sXi[i]  = Xi[(size_t)(rbase + row) * 45 + cPERM[f]] + cPBASE[f];
        sXvs[i] = Xv[(size_t)(rbase + row) * 45 + cPERM[f]];
    }
    if (t < 32) sS[t] = 0.f;
    __syncthreads();

    const int w = t >> 5, lane = t & 31;
    float macc[32];
#pragma unroll
    for (int k = 0; k < 32; ++k) macc[k] = 0.f;
    float ssum = 0.f;

#pragma unroll
    for (int i = 0; i < 8; ++i) {
        const int r = w + i * 8;
        const size_t gr = rbase + r;
        float x = g_x1p[gr * 32 + lane] + g_x1p[(NS + gr) * 32 + lane];
#pragma unroll
        for (int f = 0; f < 24; ++f)
            x = fmaf(sXvs[r * 24 + f], g_P[(size_t)sXi[r * 24 + f] * 32 + lane], x);
        g_x1s[gr * 32 + lane] = x;
        ssum += x;
#pragma unroll
        for (int k = 0; k < 32; ++k)
            macc[k] = fmaf(x, __shfl_sync(0xffffffffu, x, k), macc[k]);
    }

    atomicAdd(&sS[lane], ssum);
#pragma unroll
    for (int k = 0; k < 32; ++k)
        sMw[w * 1024 + k * 32 + lane] = macc[k];   // sMw[w][k][lane] = M[lane][k]
    __syncthreads();

    for (int e = t; e < 1024; e += 256) {
        const int k = e >> 5, i = e & 31;
        float m = 0.f;
#pragma unroll
        for (int ww = 0; ww < 8; ++ww) m += sMw[ww * 1024 + k * 32 + i];
        atomicAdd(&g_M[i * 32 + k], m);
    }
    if (t < 32) atomicAdd(&g_acc[t], sS[t]);
}

// ---------------------------------------------------------------------------
// solve: 1 block x 1024. Reads g_M once; computes w~ and C.
// ---------------------------------------------------------------------------
__global__ __launch_bounds__(1024) void solve_kernel(const float* __restrict__ l2w,
                                                     const float* __restrict__ bn1g,
                                                     const float* __restrict__ bn2g,
                                                     const float* __restrict__ bn2b,
                                                     const float* __restrict__ bias)
{
    __shared__ float sCov[1024], sM1[32], sSc1[32], sSc2[32];
    const int t = threadIdx.x;

    const float msum = g_M[t];
    if (t < 32) sM1[t] = g_acc[t] * (1.f / NS);
    __syncthreads();
    sCov[t] = msum * (1.f / NS) - sM1[t >> 5] * sM1[t & 31];
    __syncthreads();
    if (t < 32) sSc1[t] = bn1g[t] * rsqrtf(sCov[t * 32 + t] + 1e-5f);
    __syncthreads();

    const int j = t >> 5, lane = t & 31;
    const float wd = l2w[j * 32 + lane] * sSc1[lane];
    float a = 0.f;
#pragma unroll
    for (int k = 0; k < 32; ++k)
        a = fmaf(sCov[lane * 32 + k], __shfl_sync(0xffffffffu, wd, k), a);
    float p = wd * a;
#pragma unroll
    for (int o = 16; o > 0; o >>= 1) p += __shfl_xor_sync(0xffffffffu, p, o);
    if (lane == 0) sSc2[j] = bn2g[j] * rsqrtf(p + 1e-5f);
    __syncthreads();

    if (t < 32) {
        float wt = 0.f;
#pragma unroll
        for (int jj = 0; jj < 32; ++jj)
            wt = fmaf(l2w[jj * 32 + t], sSc2[jj], wt);
        wt *= sSc1[t];
        g_acc[64 + t] = wt;
        float c = bn2b[t] - wt * sM1[t];
#pragma unroll
        for (int o = 16; o > 0; o >>= 1) c += __shfl_xor_sync(0xffffffffu, c, o);
        if (t == 0) g_acc[96] = c + bias[0];
    }
}

// ---------------------------------------------------------------------------
// final: out[n] = fmp + fms + C + w~ . x1[n]
// ---------------------------------------------------------------------------
__global__ __launch_bounds__(256) void final_kernel(float* __restrict__ out)
{
    __shared__ float sw[32];
    __shared__ float sC;
    const int t = threadIdx.x;
    if (t < 32) sw[t] = g_acc[64 + t];
    if (t == 0) sC = g_acc[96];
    __syncthreads();

    const int n = blockIdx.x * 256 + t;
    float a = g_fmp[n] + g_fmp[NS + n] + g_fms[n] + sC;
    const float4* x = (const float4*)(g_x1s + (size_t)n * 32);
#pragma unroll
    for (int c = 0; c < 8; ++c) {
        float4 v = x[c];
        a = fmaf(v.x, sw[c*4+0], a);
        a = fmaf(v.y, sw[c*4+1], a);
        a = fmaf(v.z, sw[c*4+2], a);
        a = fmaf(v.w, sw[c*4+3], a);
    }
    out[n] = a;
}

// ---------------------------------------------------------------------------
extern "C" void kernel_launch(void* const* d_in, const int* in_sizes, int n_in,
                              void* d_out, int out_size)
{
    const int*   Xi    = (const int*)  d_in[0];
    const float* Xv    = (const float*)d_in[1];
    const float* W1    = (const float*)d_in[2];
    const float* W2    = (const float*)d_in[3];
    const float* bias  = (const float*)d_in[4];
    const float* l1_w  = (const float*)d_in[5];
    // d_in[6] = l1_b: cancels exactly inside BN1
    const float* bn1_g = (const float*)d_in[7];
    // d_in[8] = bn1_b: cancels exactly in the collapsed tail
    const float* l2_w  = (const float*)d_in[9];
    // d_in[10] = l2_b: cancels exactly (x2 - mean2)
    const float* bn2_g = (const float*)d_in[11];
    const float* bn2_b = (const float*)d_in[12];
    float* out = (float*)d_out;

    cudaFuncSetAttribute(k1_kernel, cudaFuncAttributeMaxDynamicSharedMemorySize, K1_DYN);

    fusedall_kernel<<<1792, 256>>>(Xi, Xv, W1, W2, l1_w);
    k1_kernel<<<256, 256, K1_DYN>>>(Xi, Xv, W1, W2);
    statsM_kernel<<<128, 256>>>(Xi, Xv);
    solve_kernel<<<1, 1024>>>(l2_w, bn1_g, bn2_g, bn2_b, bias);
    final_kernel<<<32, 256>>>(out);
}

// round 17
// speedup vs baseline: 1.1187x; 1.1187x over previous
#include <cuda_runtime.h>
#include <cuda_bf16.h>
#include <cstdint>
#include <cstddef>

#define NS   8192
#define KTOT 11520

__constant__ int cPERM[45] = {
    0,1,2,3,4,5,6, 7,8,9,
    10,11,12,13,14,15,16,17,18,19,20,21,22,23,
    26,27, 28,29, 24,25,
    30,31,32,33,34,35,36,37,38,39,40,41,42,43,44
};
__constant__ int cFOFF[45] = {
    0,300,1300,2300,2800,2950,2962,
    2993,2993,2993,
    3023,3023,3023,3023,3023,3023,3023,3023,3023,3023,3023,3023,3023,3023,
    3223,3223, 53223,53223, 103223,103223,
    123223,123223,123223,123223,123223,123223,123223,123223,
    123223,123223,123223,123223,123223,123223,123223
};
__constant__ int cVOC[24] = {
    300,1000,1000,500,150,12,31,30,30,30,
    200,200,200,200,200,200,200,200,200,200,200,200,200,200
};
__constant__ int cPBASE[24] = {
    0,300,1300,2300,2800,2950,2962,2993,3023,3053,
    3083,3283,3483,3683,3883,4083,4283,4483,4683,4883,5083,5283,5483,5683
};
#define PROWS 5883
#define TAIL_BLOCKS 512u

// device-global scratch (no cudaMalloc allowed)
__device__ __align__(16) float g_x1p[2*NS*32];
__device__ __align__(16) float g_fmp[2*NS];
__device__ __align__(16) float g_fms[NS];
__device__ __align__(16) float g_acc[128];       // [sum1|ss1|sum2|ss2] x32
__device__ __align__(16) float g_ssmall[4*NS*64];
__device__ __align__(16) float g_P[PROWS*32];
__device__ unsigned int g_bar[2];
__device__ __align__(16) unsigned char g_Bh[180*4096];
__device__ __align__(16) unsigned char g_Bl[180*4096];

// ---------------- helpers ----------------
__device__ __forceinline__ uint32_t smem_u32(const void* p) {
    uint32_t r;
    asm("{ .reg .u64 t; cvta.to.shared.u64 t, %1; cvt.u32.u64 %0, t; }"
        : "=r"(r) : "l"(p));
    return r;
}
__device__ __forceinline__ uint32_t cvt2(float hi, float lo) {
    uint32_t r;
    asm("cvt.rn.bf16x2.f32 %0, %1, %2;" : "=r"(r) : "f"(hi), "f"(lo));
    return r;
}
__device__ __forceinline__ void ldsm4(uint32_t* r, uint32_t addr) {
    asm volatile("ldmatrix.sync.aligned.m8n8.x4.shared.b16 {%0,%1,%2,%3}, [%4];"
        : "=r"(r[0]), "=r"(r[1]), "=r"(r[2]), "=r"(r[3]) : "r"(addr));
}
__device__ __forceinline__ void mma16816(float* d, const uint32_t* a, const uint32_t* b) {
    asm volatile(
        "mma.sync.aligned.m16n8k16.row.col.f32.bf16.bf16.f32 "
        "{%0,%1,%2,%3}, {%4,%5,%6,%7}, {%8,%9}, {%0,%1,%2,%3};"
        : "+f"(d[0]), "+f"(d[1]), "+f"(d[2]), "+f"(d[3])
        : "r"(a[0]), "r"(a[1]), "r"(a[2]), "r"(a[3]), "r"(b[0]), "r"(b[1]));
}
__device__ __forceinline__ void cpa16(uint32_t dst, const void* src) {
    asm volatile("cp.async.cg.shared.global [%0], [%1], 16;" :: "r"(dst), "l"(src));
}
__device__ __forceinline__ void cpa_commit() {
    asm volatile("cp.async.commit_group;" ::: "memory");
}
template<int N>
__device__ __forceinline__ void cpa_wait() {
    asm volatile("cp.async.wait_group %0;" :: "n"(N) : "memory");
}
__device__ __forceinline__ void gridbar(int id) {
    __syncthreads();
    if (threadIdx.x == 0) {
        __threadfence();
        atomicAdd(&g_bar[id], 1u);
        while (*((volatile unsigned int*)&g_bar[id]) < TAIL_BLOCKS) { }
    }
    __syncthreads();
}

// ---------------- k1 smem layout ----------------
#define A_IMG   9216u
#define SM_A(buf,img)  ((uint32_t)(((buf)*2u + (img)) * A_IMG))
#define B_IMG   4608u
#define SM_B(buf,img)  ((uint32_t)(36864u + ((buf)*2u + (img)) * B_IMG))
#define SM_IDX  73728u
#define SM_XVo  79104u
#define K1_DYN  84480u

// ---------------------------------------------------------------------------
// fusedAll: grid 1792 x 256.
//  blocks [0,768): prepP (+ blocks <180, threads <128: B tile images)
//  blocks [768,1792): small-field s/q/W1 per sample (1 warp per sample)
// ---------------------------------------------------------------------------
__global__ __launch_bounds__(256) void fusedall_kernel(const int*   __restrict__ Xi,
                                                       const float* __restrict__ Xv,
                                                       const float* __restrict__ W1,
                                                       const float* __restrict__ W2,
                                                       const float* __restrict__ l1w)
{
    const int t = threadIdx.x;

    if (blockIdx.x >= 768) {
        const int lane = t & 31;
        const int n = (blockIdx.x - 768) * 8 + (t >> 5);

        float s[8];
#pragma unroll
        for (int i = 0; i < 8; ++i) s[i] = 0.f;
        float q = 0.f, fm = 0.f;

#pragma unroll
        for (int f = 0; f < 24; ++f) {
            const int   xi = Xi[(size_t)n * 45 + cPERM[f]];
            const float xv = Xv[(size_t)n * 45 + cPERM[f]];
            const int   row = xi + cFOFF[f];
            const float4* r4 = (const float4*)(W2 + (size_t)row * 256) + lane * 2;
            float4 a = r4[0], b = r4[1];
            float e0 = a.x*xv, e1 = a.y*xv, e2 = a.z*xv, e3 = a.w*xv;
            float e4 = b.x*xv, e5 = b.y*xv, e6 = b.z*xv, e7 = b.w*xv;
            s[0]+=e0; s[1]+=e1; s[2]+=e2; s[3]+=e3;
            s[4]+=e4; s[5]+=e5; s[6]+=e6; s[7]+=e7;
            q = fmaf(e0,e0,q); q = fmaf(e1,e1,q); q = fmaf(e2,e2,q); q = fmaf(e3,e3,q);
            q = fmaf(e4,e4,q); q = fmaf(e5,e5,q); q = fmaf(e6,e6,q); q = fmaf(e7,e7,q);
            if (lane == f) fm = fmaf(W1[row], xv, fm);
        }

        float* dst = g_ssmall + ((size_t)(lane >> 3) * NS + n) * 64 + (lane & 7) * 8;
        *(float4*)(dst)     = make_float4(s[0], s[1], s[2], s[3]);
        *(float4*)(dst + 4) = make_float4(s[4], s[5], s[6], s[7]);

        float val = fm - 0.5f * q;
#pragma unroll
        for (int o = 16; o > 0; o >>= 1) val += __shfl_xor_sync(0xffffffffu, val, o);
        if (lane == 0) g_fms[n] = val;
        return;
    }

    if (blockIdx.x == 0 && t < 128) g_acc[t] = 0.f;
    if (blockIdx.x == 0 && t == 128) { g_bar[0] = 0u; g_bar[1] = 0u; }

    if (blockIdx.x < 180 && t < 128) {
        const int sid = blockIdx.x;
        const int q = sid / 45, f = sid % 45;
        const int j  = t >> 2;
        const int c0 = (t & 3) * 16;
        const float* src = l1w + (size_t)j * KTOT + f * 256 + q * 64 + c0;
        unsigned char* bh = g_Bh + (size_t)sid * 4096;
        unsigned char* bl = g_Bl + (size_t)sid * 4096;
#pragma unroll
        for (int i = 0; i < 16; i += 2) {
            float a = src[i], b = src[i+1];
            uint32_t h2 = cvt2(b, a);
            float fa = __uint_as_float(h2 << 16);
            float fb = __uint_as_float(h2 & 0xffff0000u);
            uint32_t l2 = cvt2(b - fb, a - fa);
            uint32_t off = (uint32_t)(j * 128 + (c0 + i) * 2);
            *(uint32_t*)(bh + off) = h2;
            *(uint32_t*)(bl + off) = l2;
        }
    }

    const int f = blockIdx.x >> 5;
    const int v0 = (blockIdx.x & 31) * 32;
    if (v0 >= cVOC[f]) return;
    __shared__ __align__(16) float sl[32 * 260];
    for (int i = t; i < 8192; i += 256)
        sl[(i >> 8) * 260 + (i & 255)] = l1w[(size_t)(i >> 8) * KTOT + f * 256 + (i & 255)];
    __syncthreads();

    const int rloc = t >> 3;
    const int j0   = (t & 7) * 4;
    const int v = v0 + rloc;
    if (v >= cVOC[f]) return;
    const float* wrow = W2 + (size_t)(v + cFOFF[f]) * 256;
    float acc0 = 0.f, acc1 = 0.f, acc2 = 0.f, acc3 = 0.f;
    for (int d = 0; d < 256; d += 4) {
        float4 w = *(const float4*)(wrow + d);
        float4 a0 = *(const float4*)(sl + (j0+0) * 260 + d);
        float4 a1 = *(const float4*)(sl + (j0+1) * 260 + d);
        float4 a2 = *(const float4*)(sl + (j0+2) * 260 + d);
        float4 a3 = *(const float4*)(sl + (j0+3) * 260 + d);
        acc0 += w.x*a0.x + w.y*a0.y + w.z*a0.z + w.w*a0.w;
        acc1 += w.x*a1.x + w.y*a1.y + w.z*a1.z + w.w*a1.w;
        acc2 += w.x*a2.x + w.y*a2.y + w.z*a2.z + w.w*a2.w;
        acc3 += w.x*a3.x + w.y*a3.y + w.z*a3.z + w.w*a3.w;
    }
    float* dst = g_P + (size_t)(cPBASE[f] + v) * 32 + j0;
    dst[0] = acc0; dst[1] = acc1; dst[2] = acc2; dst[3] = acc3;
}

// ---- k1 inner-phase helpers ----
__device__ __forceinline__ void convert_store(const float4* v, float xv,
    unsigned char* Ah, unsigned char* Al, uint32_t aw,
    float* s, float& qsum)
{
#pragma unroll
    for (int i = 0; i < 4; ++i) {
        float4 vv = v[i];
        float e0 = vv.x * xv, e1 = vv.y * xv;
        float e2 = vv.z * xv, e3 = vv.w * xv;
        uint32_t h01 = cvt2(e1, e0), h23 = cvt2(e3, e2);
        float f0 = __uint_as_float(h01 << 16);
        float f1 = __uint_as_float(h01 & 0xffff0000u);
        float f2 = __uint_as_float(h23 << 16);
        float f3 = __uint_as_float(h23 & 0xffff0000u);
        uint32_t l01 = cvt2(e1 - f1, e0 - f0), l23 = cvt2(e3 - f3, e2 - f2);
        *(uint2*)(Ah + aw + i * 8) = make_uint2(h01, h23);
        *(uint2*)(Al + aw + i * 8) = make_uint2(l01, l23);
        const int ii = i * 4;
        s[ii+0] += e0; qsum = fmaf(e0, e0, qsum);
        s[ii+1] += e1; qsum = fmaf(e1, e1, qsum);
        s[ii+2] += e2; qsum = fmaf(e2, e2, qsum);
        s[ii+3] += e3; qsum = fmaf(e3, e3, qsum);
    }
}

__device__ __forceinline__ void mma_stage(uint32_t aAh, uint32_t aAl,
    uint32_t aBh, uint32_t aBl, float (&acc)[2][4])
{
#pragma unroll
    for (int k = 0; k < 4; ++k) {
        uint32_t Afh[4], Afl[4], Bh[4], Bl[4];
        ldsm4(Afh, aAh + k * 32);
        ldsm4(Afl, aAl + k * 32);
        ldsm4(Bh,  aBh + k * 32);
        ldsm4(Bl,  aBl + k * 32);
        mma16816(acc[0], Afh, &Bh[0]);
        mma16816(acc[1], Afh, &Bh[2]);
        mma16816(acc[0], Afh, &Bl[0]);
        mma16816(acc[1], Afh, &Bl[2]);
        mma16816(acc[0], Afl, &Bh[0]);
        mma16816(acc[1], Afl, &Bh[2]);
    }
}

// ---------------------------------------------------------------------------
// k1: BIG fields only. 256 blocks x 256 threads, 2 CTAs/SM. (R11 version)
// ---------------------------------------------------------------------------
__global__ void __launch_bounds__(256, 2) k1_kernel(
    const int*   __restrict__ Xi,
    const float* __restrict__ Xv,
    const float* __restrict__ W1,
    const float* __restrict__ W2)
{
    extern __shared__ unsigned char dyn[];
    const uint32_t sbase = smem_u32(dyn);

    const int t    = threadIdx.x;
    const int wid  = t >> 5, lane = t & 31;
    const int tile = blockIdx.x >> 1, ks = blockIdx.x & 1;
    const int n0   = tile * 64;

    int*   sIdx = (int*)(dyn + SM_IDX);
    float* sXv  = (float*)(dyn + SM_XVo);
    for (int i = t; i < 64 * 21; i += 256) {
        const int smp = i / 21, fi = i - smp * 21;
        sIdx[i] = Xi[(size_t)(n0 + smp) * 45 + cPERM[24 + fi]] + cFOFF[24 + fi];
        sXv[i]  = Xv[(size_t)(n0 + smp) * 45 + cPERM[24 + fi]];
    }
    __syncthreads();

    const int smp = t >> 2, p = t & 3;
    const uint32_t aw = (uint32_t)(smp * 144 + p * 32);

    const int wm = wid & 3, nh = wid >> 2;
    const uint32_t a_row = (uint32_t)(wm * 16 + ((lane >> 3) & 1) * 8 + (lane & 7));
    const uint32_t a_col = (uint32_t)((lane >> 4) * 16);
    const uint32_t b_row = (uint32_t)(nh * 16 + (lane & 7) + ((lane >> 4) << 3));
    const uint32_t b_col = (uint32_t)(((lane >> 3) & 1) * 16);
    const uint32_t aoff  = a_row * 144 + a_col;
    const uint32_t boff  = b_row * 144 + b_col;

    const int bc = t & 255;
    const uint32_t bso = (uint32_t)((bc >> 3) * 128 + (bc & 7) * 16);
    const uint32_t bdo = (uint32_t)((bc >> 3) * 144 + (bc & 7) * 16);

    float acc[2][4];
#pragma unroll
    for (int i = 0; i < 2; ++i)
#pragma unroll
        for (int j = 0; j < 4; ++j) acc[i][j] = 0.f;

    float s[16];
#pragma unroll
    for (int i = 0; i < 16; ++i) s[i] = 0.f;
    float sq2 = 0.f, qsum = 0.f, fm1 = 0.f;

    float4 v[2][4];
    float  xvq[2], w1q[2];

#define ISSUE_B(tgt, BUF)  do {                                              \
        const int fi_ = (tgt) < 21 ? (tgt) : (tgt) - 21;                     \
        const size_t sb_ = (size_t)((ks * 2 + ((tgt) >= 21)) * 45 + 24 + fi_) * 4096; \
        cpa16(sbase + SM_B((BUF), 0) + bdo, g_Bh + sb_ + bso);               \
        cpa16(sbase + SM_B((BUF), 1) + bdo, g_Bl + sb_ + bso);               \
        cpa_commit();                                                        \
    } while (0)

#define LOAD_A(tgt, AB)  do {                                                \
        const int fi_ = (tgt) < 21 ? (tgt) : (tgt) - 21;                     \
        const int qg_ = ks * 2 + ((tgt) >= 21);                              \
        const int idx_ = sIdx[smp * 21 + fi_];                               \
        xvq[AB] = sXv[smp * 21 + fi_];                                       \
        w1q[AB] = (ks == 0 && (tgt) < 21 && p == 0) ? W1[idx_] : 0.f;        \
        const float4* src_ = (const float4*)(W2 + (size_t)idx_ * 256)        \
                             + qg_ * 16 + p * 4;                             \
        v[AB][0] = src_[0]; v[AB][1] = src_[1];                              \
        v[AB][2] = src_[2]; v[AB][3] = src_[3];                              \
    } while (0)

#define FOLD(qg)  do {                                                       \
        const float4* ssm_ = (const float4*)(g_ssmall                        \
            + ((size_t)(qg) * NS + n0 + smp) * 64 + p * 16);                 \
        float4 a0_ = ssm_[0], a1_ = ssm_[1], a2_ = ssm_[2], a3_ = ssm_[3];   \
        s[0]+=a0_.x; s[1]+=a0_.y; s[2]+=a0_.z; s[3]+=a0_.w;                  \
        s[4]+=a1_.x; s[5]+=a1_.y; s[6]+=a1_.z; s[7]+=a1_.w;                  \
        s[8]+=a2_.x; s[9]+=a2_.y; s[10]+=a2_.z; s[11]+=a2_.w;                \
        s[12]+=a3_.x; s[13]+=a3_.y; s[14]+=a3_.z; s[15]+=a3_.w;              \
        float loc_ = 0.f;                                                    \
        for (int i2 = 0; i2 < 16; ++i2) { loc_ += s[i2]*s[i2]; s[i2] = 0.f; }\
        sq2 += loc_;                                                         \
    } while (0)

#define STAGE(st, AB, BB, PRE, WAITN)  do {                                  \
        if (PRE) ISSUE_B((st) + 2, ((BB) + 2) & 3);                          \
        if ((st) == 21) FOLD(ks * 2);                                        \
        fm1 += w1q[AB] * xvq[AB];                                            \
        convert_store(v[AB], xvq[AB], dyn + SM_A(AB,0), dyn + SM_A(AB,1),    \
                      aw, s, qsum);                                          \
        if (PRE) LOAD_A((st) + 2, AB);                                       \
        cpa_wait<WAITN>();                                                   \
        __syncthreads();                                                     \
        mma_stage(sbase + SM_A(AB,0) + aoff, sbase + SM_A(AB,1) + aoff,      \
                  sbase + SM_B(BB,0) + boff, sbase + SM_B(BB,1) + boff, acc);\
    } while (0)

    ISSUE_B(0, 0);
    ISSUE_B(1, 1);
    LOAD_A(0, 0);
    LOAD_A(1, 1);

    for (int ii = 0; ii < 40; ii += 4) {
        STAGE(ii + 0, 0, 0, true, 2);
        STAGE(ii + 1, 1, 1, true, 2);
        STAGE(ii + 2, 0, 2, true, 2);
        STAGE(ii + 3, 1, 3, true, 2);
    }
    STAGE(40, 0, 0, false, 1);
    STAGE(41, 1, 1, false, 0);

    FOLD(ks * 2 + 1);

#undef STAGE
#undef FOLD
#undef LOAD_A
#undef ISSUE_B

    float val = fm1 + 0.5f * sq2 - 0.5f * qsum;
    val += __shfl_xor_sync(0xffffffffu, val, 1);
    val += __shfl_xor_sync(0xffffffffu, val, 2);
    if ((t & 3) == 0) g_fmp[ks * NS + n0 + smp] = val;

    {
        const int r0 = n0 + wm * 16 + (lane >> 2);
        const int cb = nh * 16 + (lane & 3) * 2;
        float* dst = g_x1p + (size_t)ks * NS * 32;
#pragma unroll
        for (int nt = 0; nt < 2; ++nt) {
            const int c = cb + nt * 8;
            *(float2*)(dst + (size_t)r0       * 32 + c) = make_float2(acc[nt][0], acc[nt][1]);
            *(float2*)(dst + (size_t)(r0 + 8) * 32 + c) = make_float2(acc[nt][2], acc[nt][3]);
        }
    }
}

// ---------------------------------------------------------------------------
// tail: single-wave 512 blocks x 256 threads with 2 grid barriers.
// phase1: x1 = x1a+x1b+P lookups (registers), BN1 sums -> g_acc[0..63]
// phase2: h = BN1(x1); x2 = h@l2w^T+l2b via shfl (registers), BN2 sums
// phase3: out = fm + sum_j BN2(x2) + bias
// ---------------------------------------------------------------------------
__global__ void __launch_bounds__(256, 4) tail_kernel(
    const int*   __restrict__ Xi,
    const float* __restrict__ Xv,
    const float* __restrict__ l2w,
    const float* __restrict__ l2b,
    const float* __restrict__ bn1g,
    const float* __restrict__ bn1b,
    const float* __restrict__ bn2g,
    const float* __restrict__ bn2b,
    const float* __restrict__ bias,
    float* __restrict__ out)
{
    __shared__ float swT[1024];
    __shared__ int   sXi[16*24];
    __shared__ float sXvs[16*24];
    __shared__ float sS[32], sQ[32], sS2[32], sQ2[32];
    __shared__ float sP1m[32], sP1s[32], sP1b[32], sLb[32];
    __shared__ float sP2m[32], sP2s[32], sP2b[32];

    const int t = threadIdx.x;
    const int w = t >> 5, lane = t & 31;
    const int rbase = blockIdx.x * 16;

    for (int i = t; i < 1024; i += 256)
        swT[(i & 31) * 32 + (i >> 5)] = l2w[i];           // swT[i][j]
    for (int i = t; i < 16 * 24; i += 256) {
        const int row = i / 24, f = i - row * 24;
        sXi[i]  = Xi[(size_t)(rbase + row) * 45 + cPERM[f]] + cPBASE[f];
        sXvs[i] = Xv[(size_t)(rbase + row) * 45 + cPERM[f]];
    }
    if (t < 32) { sS[t] = 0.f; sQ[t] = 0.f; sS2[t] = 0.f; sQ2[t] = 0.f; }
    __syncthreads();

    // ---- phase 1: combined x1 in registers ----
    float x1v[2];
#pragma unroll
    for (int g = 0; g < 2; ++g) {
        const int r = w + g * 8;
        const size_t gr = rbase + r;
        float x = g_x1p[gr * 32 + lane] + g_x1p[(NS + gr) * 32 + lane];
#pragma unroll
        for (int f = 0; f < 24; ++f)
            x = fmaf(sXvs[r * 24 + f], g_P[(size_t)sXi[r * 24 + f] * 32 + lane], x);
        x1v[g] = x;
    }
    atomicAdd(&sS[lane], x1v[0] + x1v[1]);
    atomicAdd(&sQ[lane], x1v[0]*x1v[0] + x1v[1]*x1v[1]);
    __syncthreads();
    if (t < 32) {
        atomicAdd(&g_acc[t],      sS[t]);
        atomicAdd(&g_acc[32 + t], sQ[t]);
    }
    gridbar(0);

    // ---- phase 2: BN1 + layer2 in registers ----
    if (t < 32) {
        float m   = __ldcg(&g_acc[t]) * (1.f / NS);
        float var = __ldcg(&g_acc[32 + t]) * (1.f / NS) - m * m;
        sP1m[t] = m; sP1s[t] = bn1g[t] * rsqrtf(var + 1e-5f);
        sP1b[t] = bn1b[t]; sLb[t] = l2b[t];
    }
    __syncthreads();

    float x2v[2];
#pragma unroll
    for (int g = 0; g < 2; ++g) {
        const float h = (x1v[g] - sP1m[lane]) * sP1s[lane] + sP1b[lane];
        float a = sLb[lane];
#pragma unroll
        for (int i = 0; i < 32; ++i)
            a = fmaf(__shfl_sync(0xffffffffu, h, i), swT[i * 32 + lane], a);
        x2v[g] = a;
    }
    atomicAdd(&sS2[lane], x2v[0] + x2v[1]);
    atomicAdd(&sQ2[lane], x2v[0]*x2v[0] + x2v[1]*x2v[1]);
    __syncthreads();
    if (t < 32) {
        atomicAdd(&g_acc[64 + t], sS2[t]);
        atomicAdd(&g_acc[96 + t], sQ2[t]);
    }
    gridbar(1);

    // ---- phase 3: BN2 + row sum + output ----
    if (t < 32) {
        float m   = __ldcg(&g_acc[64 + t]) * (1.f / NS);
        float var = __ldcg(&g_acc[96 + t]) * (1.f / NS) - m * m;
        sP2m[t] = m; sP2s[t] = bn2g[t] * rsqrtf(var + 1e-5f); sP2b[t] = bn2b[t];
    }
    __syncthreads();

    const float b0 = bias[0];
#pragma unroll
    for (int g = 0; g < 2; ++g) {
        float vv = (x2v[g] - sP2m[lane]) * sP2s[lane] + sP2b[lane];
#pragma unroll
        for (int o = 16; o > 0; o >>= 1) vv += __shfl_xor_sync(0xffffffffu, vv, o);
        if (lane == 0) {
            const int n = rbase + w + g * 8;
            out[n] = vv + g_fmp[n] + g_fmp[NS + n] + g_fms[n] + b0;
        }
    }
}

// ---------------------------------------------------------------------------
extern "C" void kernel_launch(void* const* d_in, const int* in_sizes, int n_in,
                              void* d_out, int out_size)
{
    const int*   Xi    = (const int*)  d_in[0];
    const float* Xv    = (const float*)d_in[1];
    const float* W1    = (const float*)d_in[2];
    const float* W2    = (const float*)d_in[3];
    const float* bias  = (const float*)d_in[4];
    const float* l1_w  = (const float*)d_in[5];
    // d_in[6] = l1_b: cancels exactly inside BN1
    const float* bn1_g = (const float*)d_in[7];
    const float* bn1_b = (const float*)d_in[8];
    const float* l2_w  = (const float*)d_in[9];
    const float* l2_b  = (const float*)d_in[10];
    const float* bn2_g = (const float*)d_in[11];
    const float* bn2_b = (const float*)d_in[12];
    float* out = (float*)d_out;

    cudaFuncSetAttribute(k1_kernel, cudaFuncAttributeMaxDynamicSharedMemorySize, K1_DYN);

    fusedall_kernel<<<1792, 256>>>(Xi, Xv, W1, W2, l1_w);
    k1_kernel<<<256, 256, K1_DYN>>>(Xi, Xv, W1, W2);
    tail_kernel<<<TAIL_BLOCKS, 256>>>(Xi, Xv, l2_w, l2_b, bn1_g, bn1_b,
                                      bn2_g, bn2_b, bias, out);
}